// round 2
// baseline (speedup 1.0000x reference)
#include <cuda_runtime.h>
#include <cstdint>

#define NG 4000      // genomes
#define NS 2048      // samples
#define NM 28000     // genes
#define NK 16000     // unique seqs

// Scratch (allocation-free: __device__ globals)
__device__ int   k_count[NK];        // histogram / scatter cursors
__device__ int   k_offset[NK + 1];   // CSR offsets per seq
__device__ int   slot_n[NM];         // payload: genome index per CSR slot
__device__ float slot_p[NM];         // payload: pos per CSR slot

__device__ __forceinline__ float ex2f(float x) {
    float y;
    asm("ex2.approx.ftz.f32 %0, %1;" : "=f"(y) : "f"(x));
    return y;
}

// ---------------- Pass 0: zero seq counters ----------------
__global__ void init_kernel() {
    int i = blockIdx.x * blockDim.x + threadIdx.x;
    if (i < NK) k_count[i] = 0;
}

// ---------------- Pass 1: histogram genes per seq ----------------
__global__ void hist_kernel(const int* __restrict__ seq_idx) {
    int g = blockIdx.x * blockDim.x + threadIdx.x;
    if (g < NM) atomicAdd(&k_count[seq_idx[g]], 1);
}

// ---------------- Pass 2: exclusive scan over NK counters (1 CTA) -------
#define SCAN_T 1024
#define VPT ((NK + SCAN_T - 1) / SCAN_T)   // 16 values per thread
__global__ void scan_kernel() {
    __shared__ int sh[SCAN_T];
    const int tid  = threadIdx.x;
    const int base = tid * VPT;
    int vals[VPT];
    int local = 0;
#pragma unroll
    for (int i = 0; i < VPT; i++) {
        int idx = base + i;
        int v = (idx < NK) ? k_count[idx] : 0;
        vals[i] = local;             // exclusive within this thread
        local += v;
    }
    sh[tid] = local;
    __syncthreads();
    // inclusive Hillis-Steele scan over thread sums
    for (int off = 1; off < SCAN_T; off <<= 1) {
        int t = (tid >= off) ? sh[tid - off] : 0;
        __syncthreads();
        sh[tid] += t;
        __syncthreads();
    }
    int pre = (tid > 0) ? sh[tid - 1] : 0;
#pragma unroll
    for (int i = 0; i < VPT; i++) {
        int idx = base + i;
        if (idx < NK) {
            k_offset[idx] = pre + vals[i];
            k_count[idx]  = 0;       // reuse as scatter cursor
        }
    }
    if (tid == SCAN_T - 1) k_offset[NK] = sh[SCAN_T - 1];  // == NM
}

// ---------------- Pass 3: scatter (genome, pos) payload into CSR -------
__global__ void scatter_kernel(const int* __restrict__ genome_idx,
                               const int* __restrict__ seq_idx,
                               const float* __restrict__ pos) {
    int g = blockIdx.x * blockDim.x + threadIdx.x;
    if (g < NM) {
        int k = seq_idx[g];
        int p = atomicAdd(&k_count[k], 1);
        int slot = k_offset[k] + p;
        slot_n[slot] = genome_idx[g];
        slot_p[slot] = pos[g];
    }
}

// ---------------- Pass 4: seq-major fused gather, single store ----------
// grid: NK CTAs; block 512 threads; each thread owns 4 consecutive samples.
#define MAIN_THREADS 512
__global__ void __launch_bounds__(MAIN_THREADS)
main_kernel(const float* __restrict__ A, const float* __restrict__ B,
            const float* __restrict__ bias, float* __restrict__ out) {
    const int k  = blockIdx.x;                  // output seq row
    const int s0 = threadIdx.x * 4;             // sample offset (512*4 == NS)

    const int beg = k_offset[k];
    const int end = k_offset[k + 1];

    float4 acc = make_float4(0.f, 0.f, 0.f, 0.f);

    for (int i = beg; i < end; i++) {
        const int   n = slot_n[i];              // uniform broadcast load
        const float p = slot_p[i];
        const float4 a = __ldg(reinterpret_cast<const float4*>(A + (size_t)n * NS + s0));
        const float4 b = __ldg(reinterpret_cast<const float4*>(B + (size_t)n * NS + s0));
        // G = A * 2^(1 - p*B) = 2 * A * 2^(-p*B); factor the 2 into the epilogue.
        acc.x = fmaf(a.x, ex2f(-p * b.x), acc.x);
        acc.y = fmaf(a.y, ex2f(-p * b.y), acc.y);
        acc.z = fmaf(a.z, ex2f(-p * b.z), acc.z);
        acc.w = fmaf(a.w, ex2f(-p * b.w), acc.w);
    }

    const float w = 2.0f * bias[k];
    float4 o;
    o.x = w * acc.x; o.y = w * acc.y; o.z = w * acc.z; o.w = w * acc.w;
    *reinterpret_cast<float4*>(out + (size_t)k * NS + s0) = o;
}

// ---------------- launch ----------------
extern "C" void kernel_launch(void* const* d_in, const int* in_sizes, int n_in,
                              void* d_out, int out_size) {
    const float* A          = (const float*)d_in[0];   // (4000, 2048)
    const float* B          = (const float*)d_in[1];   // (4000, 2048)
    const float* bias       = (const float*)d_in[2];   // (16000,)
    const float* pos        = (const float*)d_in[3];   // (28000,)
    const int*   genome_idx = (const int*)d_in[4];     // (28000,)
    const int*   seq_idx    = (const int*)d_in[5];     // (28000,)
    float*       out        = (float*)d_out;           // (16000, 2048)

    init_kernel<<<(NK + 255) / 256, 256>>>();
    hist_kernel<<<(NM + 255) / 256, 256>>>(seq_idx);
    scan_kernel<<<1, SCAN_T>>>();
    scatter_kernel<<<(NM + 255) / 256, 256>>>(genome_idx, seq_idx, pos);

    main_kernel<<<NK, MAIN_THREADS>>>(A, B, bias, out);
}

// round 4
// speedup vs baseline: 1.1583x; 1.1583x over previous
#include <cuda_runtime.h>
#include <cstdint>

#define NG 4000      // genomes
#define NS 2048      // samples
#define NM 28000     // genes
#define NK 16000     // unique seqs

// Scratch (allocation-free: __device__ globals; zero-initialized at load)
__device__ int    k_count[NK];        // histogram / scatter cursors (0 at entry & exit of every launch)
__device__ int    k_offset[NK + 1];   // CSR offsets per seq
__device__ float2 slot_np[NM];        // payload per CSR slot: .x = genome idx (bits), .y = pos

__device__ __forceinline__ float ex2f(float x) {
    float y;
    asm("ex2.approx.ftz.f32 %0, %1;" : "=f"(y) : "f"(x));
    return y;
}

struct f8 { float v[8]; };

// 32B A/B row load: non-coherent, pin in L2 (evict_last). A+B = 64MB fits in ~126MB L2.
__device__ __forceinline__ f8 ldg_el8(const float* p) {
    unsigned r0, r1, r2, r3, r4, r5, r6, r7;
    asm("ld.global.nc.L2::evict_last.v8.b32 {%0,%1,%2,%3,%4,%5,%6,%7}, [%8];"
        : "=r"(r0), "=r"(r1), "=r"(r2), "=r"(r3),
          "=r"(r4), "=r"(r5), "=r"(r6), "=r"(r7) : "l"(p));
    f8 o;
    o.v[0] = __uint_as_float(r0); o.v[1] = __uint_as_float(r1);
    o.v[2] = __uint_as_float(r2); o.v[3] = __uint_as_float(r3);
    o.v[4] = __uint_as_float(r4); o.v[5] = __uint_as_float(r5);
    o.v[6] = __uint_as_float(r6); o.v[7] = __uint_as_float(r7);
    return o;
}

// Output stores: streaming (evict-first) so the 128MB stream never displaces A/B.
__device__ __forceinline__ void stg_cs4(float* p, float a, float b, float c, float d) {
    asm volatile("st.global.cs.v4.f32 [%0], {%1,%2,%3,%4};"
                 :: "l"(p), "f"(a), "f"(b), "f"(c), "f"(d) : "memory");
}

// ---------------- Pass 1: histogram genes per seq (k_count: 0 -> cnt) ------
__global__ void hist_kernel(const int* __restrict__ seq_idx) {
    int g = blockIdx.x * blockDim.x + threadIdx.x;
    if (g < NM) atomicAdd(&k_count[seq_idx[g]], 1);
}

// ---------------- Pass 2: exclusive scan over NK counters (1 CTA) ----------
#define SCAN_T 1024
#define VPT ((NK + SCAN_T - 1) / SCAN_T)   // 16 values per thread
__global__ void scan_kernel() {
    __shared__ int sh[SCAN_T];
    const int tid  = threadIdx.x;
    const int base = tid * VPT;
    int vals[VPT];
    int local = 0;
#pragma unroll
    for (int i = 0; i < VPT; i++) {
        int idx = base + i;
        int v = (idx < NK) ? k_count[idx] : 0;
        vals[i] = local;             // exclusive within this thread
        local += v;
    }
    sh[tid] = local;
    __syncthreads();
    for (int off = 1; off < SCAN_T; off <<= 1) {
        int t = (tid >= off) ? sh[tid - off] : 0;
        __syncthreads();
        sh[tid] += t;
        __syncthreads();
    }
    int pre = (tid > 0) ? sh[tid - 1] : 0;
#pragma unroll
    for (int i = 0; i < VPT; i++) {
        int idx = base + i;
        if (idx < NK) k_offset[idx] = pre + vals[i];
    }
    if (tid == SCAN_T - 1) k_offset[NK] = sh[SCAN_T - 1];  // == NM
}

// ------- Pass 3: scatter payload into CSR (k_count: cnt -> 0, restoring invariant)
__global__ void scatter_kernel(const int* __restrict__ genome_idx,
                               const int* __restrict__ seq_idx,
                               const float* __restrict__ pos) {
    int g = blockIdx.x * blockDim.x + threadIdx.x;
    if (g < NM) {
        int k = seq_idx[g];
        int old = atomicAdd(&k_count[k], -1);         // old: cnt..1
        int slot = k_offset[k] + old - 1;
        float2 payload;
        payload.x = __int_as_float(genome_idx[g]);
        payload.y = pos[g];
        slot_np[slot] = payload;
    }
}

// ---------------- Pass 4: seq-major fused gather, single streaming store ----
// grid: NK CTAs; 256 threads; each thread owns 8 consecutive samples (256*8 == NS).
#define MAIN_THREADS 256
__global__ void __launch_bounds__(MAIN_THREADS)
main_kernel(const float* __restrict__ A, const float* __restrict__ B,
            const float* __restrict__ bias, float* __restrict__ out) {
    const int k  = blockIdx.x;                  // output seq row
    const int s0 = threadIdx.x * 8;

    const int beg = k_offset[k];
    const int end = k_offset[k + 1];

    float acc[8];
#pragma unroll
    for (int j = 0; j < 8; j++) acc[j] = 0.f;

    int i = beg;
    // 2-gene unrolled body: two independent slot->A,B load chains in flight
    for (; i + 2 <= end; i += 2) {
        const float2 p0 = slot_np[i];
        const float2 p1 = slot_np[i + 1];
        const int n0 = __float_as_int(p0.x);
        const int n1 = __float_as_int(p1.x);
        const f8 a0 = ldg_el8(A + (size_t)n0 * NS + s0);
        const f8 b0 = ldg_el8(B + (size_t)n0 * NS + s0);
        const f8 a1 = ldg_el8(A + (size_t)n1 * NS + s0);
        const f8 b1 = ldg_el8(B + (size_t)n1 * NS + s0);
#pragma unroll
        for (int j = 0; j < 8; j++)
            acc[j] = fmaf(a0.v[j], ex2f(-p0.y * b0.v[j]), acc[j]);
#pragma unroll
        for (int j = 0; j < 8; j++)
            acc[j] = fmaf(a1.v[j], ex2f(-p1.y * b1.v[j]), acc[j]);
    }
    if (i < end) {
        const float2 p0 = slot_np[i];
        const int n0 = __float_as_int(p0.x);
        const f8 a0 = ldg_el8(A + (size_t)n0 * NS + s0);
        const f8 b0 = ldg_el8(B + (size_t)n0 * NS + s0);
#pragma unroll
        for (int j = 0; j < 8; j++)
            acc[j] = fmaf(a0.v[j], ex2f(-p0.y * b0.v[j]), acc[j]);
    }

    // G = A * 2^(1 - p*B) = 2 * A * 2^(-p*B): fold the 2 into bias.
    const float w = 2.0f * bias[k];
    float* po = out + (size_t)k * NS + s0;
    stg_cs4(po,     w * acc[0], w * acc[1], w * acc[2], w * acc[3]);
    stg_cs4(po + 4, w * acc[4], w * acc[5], w * acc[6], w * acc[7]);
}

// ---------------- launch ----------------
extern "C" void kernel_launch(void* const* d_in, const int* in_sizes, int n_in,
                              void* d_out, int out_size) {
    const float* A          = (const float*)d_in[0];   // (4000, 2048)
    const float* B          = (const float*)d_in[1];   // (4000, 2048)
    const float* bias       = (const float*)d_in[2];   // (16000,)
    const float* pos        = (const float*)d_in[3];   // (28000,)
    const int*   genome_idx = (const int*)d_in[4];     // (28000,)
    const int*   seq_idx    = (const int*)d_in[5];     // (28000,)
    float*       out        = (float*)d_out;           // (16000, 2048)

    hist_kernel<<<(NM + 255) / 256, 256>>>(seq_idx);
    scan_kernel<<<1, SCAN_T>>>();
    scatter_kernel<<<(NM + 255) / 256, 256>>>(genome_idx, seq_idx, pos);
    main_kernel<<<NK, MAIN_THREADS>>>(A, B, bias, out);
}